// round 11
// baseline (speedup 1.0000x reference)
#include <cuda_runtime.h>
#include <cuda_bf16.h>
#include <stdint.h>
#include <math.h>

// Problem constants
#define B_ 2
#define S_ 2048
#define D_ 1024
#define H_ 16
#define HD_ 64
#define M_ (B_ * S_)

// Scratch (device globals; no allocations allowed)
__device__ __nv_bfloat16 g_xhi[M_ * D_];
__device__ __nv_bfloat16 g_xlo[M_ * D_];
__device__ __nv_bfloat16 g_whi[4 * D_ * D_];   // [sel][k][n] row-major
__device__ __nv_bfloat16 g_wlo[4 * D_ * D_];
__device__ __nv_bfloat16 g_qhi[M_ * D_];
__device__ __nv_bfloat16 g_qlo[M_ * D_];
__device__ __nv_bfloat16 g_khi[M_ * D_];
__device__ __nv_bfloat16 g_klo[M_ * D_];
__device__ __nv_bfloat16 g_vhi[M_ * D_];
__device__ __nv_bfloat16 g_vlo[M_ * D_];
__device__ __nv_bfloat16 g_ahi[M_ * D_];
__device__ __nv_bfloat16 g_alo[M_ * D_];

#define QSCALE 0.1803368801111204f   // 0.125 * log2(e)

// ---------------------------------------------------------------------------
// Common helpers
// ---------------------------------------------------------------------------
__device__ __forceinline__ void cp_async16(unsigned int dst, const void* src) {
    asm volatile("cp.async.cg.shared.global [%0], [%1], 16;\n" :: "r"(dst), "l"(src));
}
__device__ __forceinline__ void cp_commit() {
    asm volatile("cp.async.commit_group;\n" ::: "memory");
}
template <int N>
__device__ __forceinline__ void cp_wait() {
    asm volatile("cp.async.wait_group %0;\n" :: "n"(N) : "memory");
}

__device__ __forceinline__ float ex2f(float x) {
    float y;
    asm("ex2.approx.ftz.f32 %0, %1;" : "=f"(y) : "f"(x));
    return y;
}

__device__ __forceinline__ void split2(float x, float y,
                                       unsigned int& hi, unsigned int& lo) {
    __nv_bfloat16 hx = __float2bfloat16_rn(x);
    __nv_bfloat16 hy = __float2bfloat16_rn(y);
    float rx = x - __bfloat162float(hx);
    float ry = y - __bfloat162float(hy);
    __nv_bfloat16 lx = __float2bfloat16_rn(rx);
    __nv_bfloat16 ly = __float2bfloat16_rn(ry);
    unsigned short hxu = *(unsigned short*)&hx;
    unsigned short hyu = *(unsigned short*)&hy;
    unsigned short lxu = *(unsigned short*)&lx;
    unsigned short lyu = *(unsigned short*)&ly;
    hi = (unsigned int)hxu | ((unsigned int)hyu << 16);
    lo = (unsigned int)lxu | ((unsigned int)lyu << 16);
}

__device__ __forceinline__ void mma_bf16(float* c, const unsigned int* a,
                                         const unsigned int* b) {
    asm volatile(
        "mma.sync.aligned.m16n8k16.row.col.f32.bf16.bf16.f32 "
        "{%0,%1,%2,%3}, {%4,%5,%6,%7}, {%8,%9}, {%0,%1,%2,%3};\n"
        : "+f"(c[0]), "+f"(c[1]), "+f"(c[2]), "+f"(c[3])
        : "r"(a[0]), "r"(a[1]), "r"(a[2]), "r"(a[3]),
          "r"(b[0]), "r"(b[1]));
}

__device__ __forceinline__ void ldsm4(unsigned int& r0, unsigned int& r1,
                                      unsigned int& r2, unsigned int& r3,
                                      unsigned int addr) {
    asm volatile("ldmatrix.sync.aligned.m8n8.x4.shared.b16 {%0,%1,%2,%3}, [%4];"
                 : "=r"(r0), "=r"(r1), "=r"(r2), "=r"(r3) : "r"(addr));
}
__device__ __forceinline__ void ldsm4t(unsigned int& r0, unsigned int& r1,
                                       unsigned int& r2, unsigned int& r3,
                                       unsigned int addr) {
    asm volatile("ldmatrix.sync.aligned.m8n8.x4.trans.shared.b16 {%0,%1,%2,%3}, [%4];"
                 : "=r"(r0), "=r"(r1), "=r"(r2), "=r"(r3) : "r"(addr));
}

// ---------------------------------------------------------------------------
// Merged fp32 -> bf16 hi/lo split kernel: x (2M pairs) + 4 weights (0.5M each)
// laid out contiguously in g_whi/g_wlo.
// ---------------------------------------------------------------------------
#define XPAIRS (M_ * D_ / 2)
#define WPAIRS (D_ * D_ / 2)

__global__ void split_all_kernel(const float* __restrict__ x,
                                 const float* __restrict__ wq,
                                 const float* __restrict__ wk,
                                 const float* __restrict__ wv,
                                 const float* __restrict__ wo,
                                 __nv_bfloat16* __restrict__ xhi,
                                 __nv_bfloat16* __restrict__ xlo,
                                 __nv_bfloat16* __restrict__ whi,
                                 __nv_bfloat16* __restrict__ wlo) {
    long t = (long)blockIdx.x * blockDim.x + threadIdx.x;
    const long total = XPAIRS + 4L * WPAIRS;
    if (t >= total) return;
    const float* src;
    __nv_bfloat16 *dhi, *dlo;
    long idx;
    if (t < XPAIRS) {
        src = x; dhi = xhi; dlo = xlo; idx = t;
    } else {
        long wt = t - XPAIRS;
        int sel = (int)(wt / WPAIRS);
        idx = wt - (long)sel * WPAIRS;
        src = (sel == 0) ? wq : (sel == 1) ? wk : (sel == 2) ? wv : wo;
        dhi = whi + (long)sel * D_ * D_;
        dlo = wlo + (long)sel * D_ * D_;
    }
    float2 u = *(const float2*)(src + idx * 2);
    unsigned int hi, lo;
    split2(u.x, u.y, hi, lo);
    *(unsigned int*)(dhi + idx * 2) = hi;
    *(unsigned int*)(dlo + idx * 2) = lo;
}

// ---------------------------------------------------------------------------
// bf16 pre-split 3-term GEMM, 256x128 block tile, 8 warps (4x2), 64x64 warp
// tile (6:1 MMA:ldmatrix), cp.async double-buffer.
// MODE 0: fp32 store. 1: rope+scale+split (Q). 2: rope+split (K). 3: split (V).
// ---------------------------------------------------------------------------
#define BM 256
#define BN 128
#define GK 32
#define ASTR 40
#define BSTR 136
#define A_ELE (BM * ASTR)                  // 10240
#define B_ELE (GK * BSTR)                  // 4352
#define STG_ELE (2 * A_ELE + 2 * B_ELE)    // 29184
#define GEMM_SMEM (STG_ELE * 2 * 2)        // 116736 bytes

template <int MODE>
__device__ __forceinline__ void gemm_core_bf16(
    const __nv_bfloat16* __restrict__ Ahi, const __nv_bfloat16* __restrict__ Alo,
    const __nv_bfloat16* __restrict__ Bhi, const __nv_bfloat16* __restrict__ Blo,
    float* __restrict__ C,
    __nv_bfloat16* __restrict__ Dhi, __nv_bfloat16* __restrict__ Dlo,
    const float* __restrict__ fc, const float* __restrict__ fs,
    int N, int K, int bm, int bn) {
    extern __shared__ __nv_bfloat16 smG[];

    const int tid = threadIdx.x;
    const int wid = tid >> 5;
    const int lane = tid & 31;
    const int wm = (wid >> 1) * 64;    // 0,64,128,192
    const int wn = (wid & 1) * 64;     // 0,64
    const int g = lane >> 2;
    const int t4 = lane & 3;
    const int grp = lane >> 3;
    const int rr = lane & 7;

    const unsigned int smbase = (unsigned int)__cvta_generic_to_shared(smG);
    const unsigned int offAhi = 0;
    const unsigned int offAlo = A_ELE;
    const unsigned int offBhi = 2 * A_ELE;
    const unsigned int offBlo = 2 * A_ELE + B_ELE;

    float cc[4][8][4];
#pragma unroll
    for (int i = 0; i < 4; i++)
#pragma unroll
        for (int j = 0; j < 8; j++)
#pragma unroll
            for (int r = 0; r < 4; r++) cc[i][j][r] = 0.f;

    const int Kt = K / GK;

    auto issue_stage = [&](int kt, int buf) {
        const unsigned int sb = smbase + (unsigned)buf * STG_ELE * 2;
        // A: 1024 chunks per array, 4 per thread
#pragma unroll
        for (int i = 0; i < 4; i++) {
            const int ch = tid + i * 256;
            const int row = ch >> 2;
            const int c = ch & 3;
            const long goff = (long)(bm + row) * K + kt * GK + c * 8;
            cp_async16(sb + (offAhi + (unsigned)(row * ASTR + c * 8)) * 2, Ahi + goff);
            cp_async16(sb + (offAlo + (unsigned)(row * ASTR + c * 8)) * 2, Alo + goff);
        }
        // B: 512 chunks per array, 2 per thread
#pragma unroll
        for (int i = 0; i < 2; i++) {
            const int ch = tid + i * 256;
            const int row = ch >> 4;
            const int c = ch & 15;
            const long goff = (long)(kt * GK + row) * N + bn + c * 8;
            cp_async16(sb + (offBhi + (unsigned)(row * BSTR + c * 8)) * 2, Bhi + goff);
            cp_async16(sb + (offBlo + (unsigned)(row * BSTR + c * 8)) * 2, Blo + goff);
        }
        cp_commit();
    };

    issue_stage(0, 0);

    for (int kt = 0; kt < Kt; kt++) {
        const int buf = kt & 1;
        if (kt + 1 < Kt) {
            issue_stage(kt + 1, buf ^ 1);
            cp_wait<1>();
        } else {
            cp_wait<0>();
        }
        __syncthreads();

        const __nv_bfloat16* sAhi = smG + buf * STG_ELE + offAhi;
        const __nv_bfloat16* sAlo = smG + buf * STG_ELE + offAlo;
        const __nv_bfloat16* sBhi = smG + buf * STG_ELE + offBhi;
        const __nv_bfloat16* sBlo = smG + buf * STG_ELE + offBlo;

#pragma unroll
        for (int ks = 0; ks < 2; ks++) {
            const int arow_in = (grp & 1) * 8 + rr;
            const int acol = ks * 16 + (grp >> 1) * 8;
            unsigned int ah[4][4], al[4][4];
#pragma unroll
            for (int mt = 0; mt < 4; mt++) {
                const int r0 = wm + mt * 16 + arow_in;
                unsigned int addr_h = (unsigned int)__cvta_generic_to_shared(
                    sAhi + r0 * ASTR + acol);
                ldsm4(ah[mt][0], ah[mt][1], ah[mt][2], ah[mt][3], addr_h);
                unsigned int addr_l = (unsigned int)__cvta_generic_to_shared(
                    sAlo + r0 * ASTR + acol);
                ldsm4(al[mt][0], al[mt][1], al[mt][2], al[mt][3], addr_l);
            }
            const int brow = ks * 16 + (grp & 1) * 8 + rr;
#pragma unroll
            for (int np = 0; np < 4; np++) {
                const int ntA = 2 * np, ntB = 2 * np + 1;
                const int colsel = wn + np * 16 + ((grp & 2) ? 8 : 0);
                unsigned int bhA[2], bhB[2], blA[2], blB[2];
                unsigned int addr_h = (unsigned int)__cvta_generic_to_shared(
                    sBhi + brow * BSTR + colsel);
                ldsm4t(bhA[0], bhA[1], bhB[0], bhB[1], addr_h);
                unsigned int addr_l = (unsigned int)__cvta_generic_to_shared(
                    sBlo + brow * BSTR + colsel);
                ldsm4t(blA[0], blA[1], blB[0], blB[1], addr_l);
#pragma unroll
                for (int mt = 0; mt < 4; mt++) {
                    mma_bf16(cc[mt][ntA], ah[mt], blA);
                    mma_bf16(cc[mt][ntA], al[mt], bhA);
                    mma_bf16(cc[mt][ntA], ah[mt], bhA);
                    mma_bf16(cc[mt][ntB], ah[mt], blB);
                    mma_bf16(cc[mt][ntB], al[mt], bhB);
                    mma_bf16(cc[mt][ntB], ah[mt], bhB);
                }
            }
        }
        __syncthreads();
    }

    // Epilogue
#pragma unroll
    for (int mt = 0; mt < 4; mt++) {
#pragma unroll
        for (int nt = 0; nt < 8; nt++) {
            const int row = bm + wm + mt * 16 + g;
            const int col = bn + wn + nt * 8 + 2 * t4;
            if (MODE == 0) {
                *(float2*)(C + (long)row * N + col) =
                    make_float2(cc[mt][nt][0], cc[mt][nt][1]);
                *(float2*)(C + (long)(row + 8) * N + col) =
                    make_float2(cc[mt][nt][2], cc[mt][nt][3]);
            } else {
                const int p = (col & 63) >> 1;
#pragma unroll
                for (int rp = 0; rp < 2; rp++) {
                    const int r = row + rp * 8;
                    float x = cc[mt][nt][rp * 2];
                    float y = cc[mt][nt][rp * 2 + 1];
                    if (MODE == 1 || MODE == 2) {
                        const int s = r & (S_ - 1);
                        float c = fc[s * 32 + p];
                        float sn = fs[s * 32 + p];
                        float xr = x * c - y * sn;
                        float yr = x * sn + y * c;
                        if (MODE == 1) { xr *= QSCALE; yr *= QSCALE; }
                        x = xr; y = yr;
                    }
                    unsigned int hi, lo;
                    split2(x, y, hi, lo);
                    *(unsigned int*)(Dhi + (long)r * N + col) = hi;
                    *(unsigned int*)(Dlo + (long)r * N + col) = lo;
                }
            }
        }
    }
}

// Merged QKV projection + RoPE + split: blockIdx.x in [0,24).
__global__ __launch_bounds__(256, 1) void qkv_gemm(
    const __nv_bfloat16* __restrict__ xhi, const __nv_bfloat16* __restrict__ xlo,
    const __nv_bfloat16* __restrict__ whi, const __nv_bfloat16* __restrict__ wlo,
    const float* __restrict__ fc, const float* __restrict__ fs,
    __nv_bfloat16* __restrict__ qhi, __nv_bfloat16* __restrict__ qlo,
    __nv_bfloat16* __restrict__ khi, __nv_bfloat16* __restrict__ klo,
    __nv_bfloat16* __restrict__ vhi, __nv_bfloat16* __restrict__ vlo) {
    const int sel = blockIdx.x >> 3;
    const int bn = (blockIdx.x & 7) * BN;
    const int bm = blockIdx.y * BM;
    const __nv_bfloat16* Whi = whi + (long)sel * D_ * D_;
    const __nv_bfloat16* Wlo = wlo + (long)sel * D_ * D_;
    if (sel == 0)
        gemm_core_bf16<1>(xhi, xlo, Whi, Wlo, nullptr, qhi, qlo, fc, fs,
                          D_, D_, bm, bn);
    else if (sel == 1)
        gemm_core_bf16<2>(xhi, xlo, Whi, Wlo, nullptr, khi, klo, fc, fs,
                          D_, D_, bm, bn);
    else
        gemm_core_bf16<3>(xhi, xlo, Whi, Wlo, nullptr, vhi, vlo, nullptr, nullptr,
                          D_, D_, bm, bn);
}

__global__ __launch_bounds__(256, 1) void out_gemm(
    const __nv_bfloat16* __restrict__ ahi, const __nv_bfloat16* __restrict__ alo,
    const __nv_bfloat16* __restrict__ whi, const __nv_bfloat16* __restrict__ wlo,
    float* __restrict__ C) {
    gemm_core_bf16<0>(ahi, alo, whi + 3L * D_ * D_, wlo + 3L * D_ * D_, C,
                      nullptr, nullptr, nullptr, nullptr,
                      D_, D_, blockIdx.y * BM, blockIdx.x * BN);
}

// ---------------------------------------------------------------------------
// Flash attention (unchanged, known-good): 64-row Q tile, 128 threads.
// Pre-split bf16 in AND out, cp.async double-buffered K/V.
// ---------------------------------------------------------------------------
#define KP 72
#define TILE_E (64 * KP)
#define FLASH_SMEM (8 * TILE_E * 2)

__global__ __launch_bounds__(128) void flash2(
    const __nv_bfloat16* __restrict__ qhi, const __nv_bfloat16* __restrict__ qlo,
    const __nv_bfloat16* __restrict__ khi, const __nv_bfloat16* __restrict__ klo,
    const __nv_bfloat16* __restrict__ vhi, const __nv_bfloat16* __restrict__ vlo,
    __nv_bfloat16* __restrict__ ohi, __nv_bfloat16* __restrict__ olo) {
    extern __shared__ __nv_bfloat16 smB[];

    const int tid = threadIdx.x;
    const int lane = tid & 31;
    const int wid = tid >> 5;
    const int g = lane >> 2;
    const int t4 = lane & 3;
    const int wrow = wid * 16;
    const int grp = lane >> 3;
    const int rr  = lane & 7;

    const int qt = blockIdx.x;
    const int bh = blockIdx.y;
    const int q0 = qt * 64;

    const long headoff = (long)(bh >> 4) * S_ * D_ + (bh & 15) * HD_;
    const __nv_bfloat16* srcp[4] = {khi + headoff, klo + headoff,
                                    vhi + headoff, vlo + headoff};

    const unsigned int smbase = (unsigned int)__cvta_generic_to_shared(smB);

    unsigned int qh[4][4], ql[4][4];
    {
        const __nv_bfloat16* qhb = qhi + headoff;
        const __nv_bfloat16* qlb = qlo + headoff;
        const long r0 = (long)(q0 + wrow + g) * D_;
        const long r1 = (long)(q0 + wrow + g + 8) * D_;
#pragma unroll
        for (int kc = 0; kc < 4; kc++) {
            const int cb = kc * 16 + 2 * t4;
            qh[kc][0] = *(const unsigned int*)(qhb + r0 + cb);
            qh[kc][1] = *(const unsigned int*)(qhb + r1 + cb);
            qh[kc][2] = *(const unsigned int*)(qhb + r0 + cb + 8);
            qh[kc][3] = *(const unsigned int*)(qhb + r1 + cb + 8);
            ql[kc][0] = *(const unsigned int*)(qlb + r0 + cb);
            ql[kc][1] = *(const unsigned int*)(qlb + r1 + cb);
            ql[kc][2] = *(const unsigned int*)(qlb + r0 + cb + 8);
            ql[kc][3] = *(const unsigned int*)(qlb + r1 + cb + 8);
        }
    }

    auto issue = [&](int jt, int buf) {
        const int k0 = jt * 64;
#pragma unroll
        for (int i = 0; i < 16; i++) {
            const int G = tid + i * 128;
            const int arr = G >> 9;
            const int rem = G & 511;
            const int row = rem >> 3;
            const int ch = rem & 7;
            unsigned int dst = smbase +
                ((unsigned)((buf * 4 + arr) * TILE_E + row * KP + ch * 8)) * 2;
            cp_async16(dst, srcp[arr] + ((long)(k0 + row) * D_ + ch * 8));
        }
        cp_commit();
    };

    float oacc[8][4];
#pragma unroll
    for (int nt = 0; nt < 8; nt++)
#pragma unroll
        for (int r = 0; r < 4; r++) oacc[nt][r] = 0.f;
    float m0 = -1e30f, m1 = -1e30f, l0 = 0.f, l1 = 0.f;

    const int ntiles = qt + 1;
    issue(0, 0);

    for (int jt = 0; jt < ntiles; jt++) {
        const int buf = jt & 1;
        if (jt + 1 < ntiles) {
            issue(jt + 1, buf ^ 1);
            cp_wait<1>();
        } else {
            cp_wait<0>();
        }
        __syncthreads();

        const __nv_bfloat16* kh_s = smB + (buf * 4 + 0) * TILE_E;
        const __nv_bfloat16* kl_s = smB + (buf * 4 + 1) * TILE_E;
        const __nv_bfloat16* vh_s = smB + (buf * 4 + 2) * TILE_E;
        const __nv_bfloat16* vl_s = smB + (buf * 4 + 3) * TILE_E;

        float sc[8][4];
#pragma unroll
        for (int nt = 0; nt < 8; nt++)
#pragma unroll
            for (int r = 0; r < 4; r++) sc[nt][r] = 0.f;

#pragma unroll
        for (int dc = 0; dc < 4; dc++) {
#pragma unroll
            for (int np = 0; np < 4; np++) {
                const int ntA = 2 * np, ntB = 2 * np + 1;
                const int keysel = (grp & 2) ? ntB : ntA;
                const int colsel = dc * 16 + ((grp & 1) ? 8 : 0);
                unsigned int ahh = (unsigned int)__cvta_generic_to_shared(
                    kh_s + (keysel * 8 + rr) * KP + colsel);
                unsigned int ahl = (unsigned int)__cvta_generic_to_shared(
                    kl_s + (keysel * 8 + rr) * KP + colsel);
                unsigned int bhA[2], bhB[2], blA[2], blB[2];
                ldsm4(bhA[0], bhA[1], bhB[0], bhB[1], ahh);
                ldsm4(blA[0], blA[1], blB[0], blB[1], ahl);
                mma_bf16(sc[ntA], qh[dc], blA);
                mma_bf16(sc[ntA], ql[dc], bhA);
                mma_bf16(sc[ntA], qh[dc], bhA);
                mma_bf16(sc[ntB], qh[dc], blB);
                mma_bf16(sc[ntB], ql[dc], bhB);
                mma_bf16(sc[ntB], qh[dc], bhB);
            }
        }

        if (jt == qt) {
            const int r0l = wrow + g;
#pragma unroll
            for (int nt = 0; nt < 8; nt++) {
                const int c = nt * 8 + 2 * t4;
                if (c > r0l)          sc[nt][0] = -1e30f;
                if (c + 1 > r0l)      sc[nt][1] = -1e30f;
                if (c > r0l + 8)      sc[nt][2] = -1e30f;
                if (c + 1 > r0l + 8)  sc[nt][3] = -1e30f;
            }
        }

        float tm0 = -1e30f, tm1 = -1e30f;
#pragma unroll
        for (int nt = 0; nt < 8; nt++) {
            tm0 = fmaxf(tm0, fmaxf(sc[nt][0], sc[nt][1]));
            tm1 = fmaxf(tm1, fmaxf(sc[nt][2], sc[nt][3]));
        }
        tm0 = fmaxf(tm0, __shfl_xor_sync(0xffffffffu, tm0, 1));
        tm0 = fmaxf(tm0, __shfl_xor_sync(0xffffffffu, tm0, 2));
        tm1 = fmaxf(tm1, __shfl_xor_sync(0xffffffffu, tm1, 1));
        tm1 = fmaxf(tm1, __shfl_xor_sync(0xffffffffu, tm1, 2));

        float mn0 = fmaxf(m0, tm0);
        float mn1 = fmaxf(m1, tm1);
        float al0 = ex2f(m0 - mn0);
        float al1 = ex2f(m1 - mn1);
        m0 = mn0; m1 = mn1;

        float ps0 = 0.f, ps1 = 0.f;
#pragma unroll
        for (int nt = 0; nt < 8; nt++) {
            sc[nt][0] = ex2f(sc[nt][0] - m0);
            sc[nt][1] = ex2f(sc[nt][1] - m0);
            sc[nt][2] = ex2f(sc[nt][2] - m1);
            sc[nt][3] = ex2f(sc[nt][3] - m1);
            ps0 += sc[nt][0] + sc[nt][1];
            ps1 += sc[nt][2] + sc[nt][3];
        }
        ps0 += __shfl_xor_sync(0xffffffffu, ps0, 1);
        ps0 += __shfl_xor_sync(0xffffffffu, ps0, 2);
        ps1 += __shfl_xor_sync(0xffffffffu, ps1, 1);
        ps1 += __shfl_xor_sync(0xffffffffu, ps1, 2);
        l0 = l0 * al0 + ps0;
        l1 = l1 * al1 + ps1;

#pragma unroll
        for (int nt = 0; nt < 8; nt++) {
            oacc[nt][0] *= al0; oacc[nt][1] *= al0;
            oacc[nt][2] *= al1; oacc[nt][3] *= al1;
        }

#pragma unroll
        for (int kc = 0; kc < 4; kc++) {
            unsigned int ph[4], pl[4];
            split2(sc[2 * kc][0], sc[2 * kc][1], ph[0], pl[0]);
            split2(sc[2 * kc][2], sc[2 * kc][3], ph[1], pl[1]);
            split2(sc[2 * kc + 1][0], sc[2 * kc + 1][1], ph[2], pl[2]);
            split2(sc[2 * kc + 1][2], sc[2 * kc + 1][3], ph[3], pl[3]);
#pragma unroll
            for (int np = 0; np < 4; np++) {
                const int ntA = 2 * np, ntB = 2 * np + 1;
                const int rowsel = kc * 16 + ((grp & 1) ? 8 : 0) + rr;
                const int colsel = ((grp & 2) ? ntB : ntA) * 8;
                unsigned int avh = (unsigned int)__cvta_generic_to_shared(
                    vh_s + rowsel * KP + colsel);
                unsigned int avl = (unsigned int)__cvta_generic_to_shared(
                    vl_s + rowsel * KP + colsel);
                unsigned int vhA[2], vhB[2], vlA[2], vlB[2];
                ldsm4t(vhA[0], vhA[1], vhB[0], vhB[1], avh);
                ldsm4t(vlA[0], vlA[1], vlB[0], vlB[1], avl);
                mma_bf16(oacc[ntA], ph, vlA);
                mma_bf16(oacc[ntA], pl, vhA);
                mma_bf16(oacc[ntA], ph, vhA);
                mma_bf16(oacc[ntB], ph, vlB);
                mma_bf16(oacc[ntB], pl, vhB);
                mma_bf16(oacc[ntB], ph, vhB);
            }
        }
        __syncthreads();
    }

    const float inv0 = 1.f / l0;
    const float inv1 = 1.f / l1;
    const int row0 = q0 + wrow + g;
    __nv_bfloat16* ohb = ohi + headoff;
    __nv_bfloat16* olb = olo + headoff;
#pragma unroll
    for (int nt = 0; nt < 8; nt++) {
        const int col = nt * 8 + 2 * t4;
        unsigned int hi, lo;
        split2(oacc[nt][0] * inv0, oacc[nt][1] * inv0, hi, lo);
        *(unsigned int*)(ohb + (long)row0 * D_ + col) = hi;
        *(unsigned int*)(olb + (long)row0 * D_ + col) = lo;
        split2(oacc[nt][2] * inv1, oacc[nt][3] * inv1, hi, lo);
        *(unsigned int*)(ohb + (long)(row0 + 8) * D_ + col) = hi;
        *(unsigned int*)(olb + (long)(row0 + 8) * D_ + col) = lo;
    }
}

// ---------------------------------------------------------------------------
// Launch
// ---------------------------------------------------------------------------
extern "C" void kernel_launch(void* const* d_in, const int* in_sizes, int n_in,
                              void* d_out, int out_size) {
    const float* x  = (const float*)d_in[0];
    const float* wq = (const float*)d_in[1];
    const float* wk = (const float*)d_in[2];
    const float* wv = (const float*)d_in[3];
    const float* wo = (const float*)d_in[4];
    const float* fc = (const float*)d_in[5];
    const float* fs = (const float*)d_in[6];
    float* out = (float*)d_out;

    __nv_bfloat16 *xhi, *xlo, *whi, *wlo;
    __nv_bfloat16 *qhi, *qlo, *khi, *klo, *vhi, *vlo, *ahi, *alo;
    cudaGetSymbolAddress((void**)&xhi, g_xhi);
    cudaGetSymbolAddress((void**)&xlo, g_xlo);
    cudaGetSymbolAddress((void**)&whi, g_whi);
    cudaGetSymbolAddress((void**)&wlo, g_wlo);
    cudaGetSymbolAddress((void**)&qhi, g_qhi);
    cudaGetSymbolAddress((void**)&qlo, g_qlo);
    cudaGetSymbolAddress((void**)&khi, g_khi);
    cudaGetSymbolAddress((void**)&klo, g_klo);
    cudaGetSymbolAddress((void**)&vhi, g_vhi);
    cudaGetSymbolAddress((void**)&vlo, g_vlo);
    cudaGetSymbolAddress((void**)&ahi, g_ahi);
    cudaGetSymbolAddress((void**)&alo, g_alo);

    const long split_total = XPAIRS + 4L * WPAIRS;
    split_all_kernel<<<(int)((split_total + 255) / 256), 256>>>(
        x, wq, wk, wv, wo, xhi, xlo, whi, wlo);

    cudaFuncSetAttribute(qkv_gemm, cudaFuncAttributeMaxDynamicSharedMemorySize,
                         GEMM_SMEM);
    cudaFuncSetAttribute(out_gemm, cudaFuncAttributeMaxDynamicSharedMemorySize,
                         GEMM_SMEM);

    qkv_gemm<<<dim3(24, M_ / BM), 256, GEMM_SMEM>>>(xhi, xlo, whi, wlo, fc, fs,
                                                    qhi, qlo, khi, klo, vhi, vlo);

    cudaFuncSetAttribute(flash2, cudaFuncAttributeMaxDynamicSharedMemorySize,
                         FLASH_SMEM);
    flash2<<<dim3(S_ / 64, B_ * H_), 128, FLASH_SMEM>>>(qhi, qlo, khi, klo,
                                                        vhi, vlo, ahi, alo);

    out_gemm<<<dim3(D_ / BN, M_ / BM), 256, GEMM_SMEM>>>(ahi, alo, whi, wlo, out);
}

// round 13
// speedup vs baseline: 1.0290x; 1.0290x over previous
#include <cuda_runtime.h>
#include <cuda_bf16.h>
#include <stdint.h>
#include <math.h>

// Problem constants
#define B_ 2
#define S_ 2048
#define D_ 1024
#define H_ 16
#define HD_ 64
#define M_ (B_ * S_)

// Scratch (device globals; no allocations allowed)
__device__ __nv_bfloat16 g_xhi[M_ * D_];
__device__ __nv_bfloat16 g_xlo[M_ * D_];
__device__ __nv_bfloat16 g_whi[4 * D_ * D_];   // [sel][k][n] row-major
__device__ __nv_bfloat16 g_wlo[4 * D_ * D_];
__device__ __nv_bfloat16 g_qhi[M_ * D_];
__device__ __nv_bfloat16 g_qlo[M_ * D_];
__device__ __nv_bfloat16 g_khi[M_ * D_];
__device__ __nv_bfloat16 g_klo[M_ * D_];
__device__ __nv_bfloat16 g_vhi[M_ * D_];
__device__ __nv_bfloat16 g_vlo[M_ * D_];
__device__ __nv_bfloat16 g_ahi[M_ * D_];
__device__ __nv_bfloat16 g_alo[M_ * D_];

#define QSCALE 0.1803368801111204f   // 0.125 * log2(e)

// ---------------------------------------------------------------------------
// Common helpers
// ---------------------------------------------------------------------------
__device__ __forceinline__ void cp_async16(unsigned int dst, const void* src) {
    asm volatile("cp.async.cg.shared.global [%0], [%1], 16;\n" :: "r"(dst), "l"(src));
}
__device__ __forceinline__ void cp_commit() {
    asm volatile("cp.async.commit_group;\n" ::: "memory");
}
template <int N>
__device__ __forceinline__ void cp_wait() {
    asm volatile("cp.async.wait_group %0;\n" :: "n"(N) : "memory");
}

__device__ __forceinline__ float ex2f(float x) {
    float y;
    asm("ex2.approx.ftz.f32 %0, %1;" : "=f"(y) : "f"(x));
    return y;
}

__device__ __forceinline__ void split2(float x, float y,
                                       unsigned int& hi, unsigned int& lo) {
    __nv_bfloat16 hx = __float2bfloat16_rn(x);
    __nv_bfloat16 hy = __float2bfloat16_rn(y);
    float rx = x - __bfloat162float(hx);
    float ry = y - __bfloat162float(hy);
    __nv_bfloat16 lx = __float2bfloat16_rn(rx);
    __nv_bfloat16 ly = __float2bfloat16_rn(ry);
    unsigned short hxu = *(unsigned short*)&hx;
    unsigned short hyu = *(unsigned short*)&hy;
    unsigned short lxu = *(unsigned short*)&lx;
    unsigned short lyu = *(unsigned short*)&ly;
    hi = (unsigned int)hxu | ((unsigned int)hyu << 16);
    lo = (unsigned int)lxu | ((unsigned int)lyu << 16);
}

__device__ __forceinline__ void mma_bf16(float* c, const unsigned int* a,
                                         const unsigned int* b) {
    asm volatile(
        "mma.sync.aligned.m16n8k16.row.col.f32.bf16.bf16.f32 "
        "{%0,%1,%2,%3}, {%4,%5,%6,%7}, {%8,%9}, {%0,%1,%2,%3};\n"
        : "+f"(c[0]), "+f"(c[1]), "+f"(c[2]), "+f"(c[3])
        : "r"(a[0]), "r"(a[1]), "r"(a[2]), "r"(a[3]),
          "r"(b[0]), "r"(b[1]));
}

__device__ __forceinline__ void ldsm4(unsigned int& r0, unsigned int& r1,
                                      unsigned int& r2, unsigned int& r3,
                                      unsigned int addr) {
    asm volatile("ldmatrix.sync.aligned.m8n8.x4.shared.b16 {%0,%1,%2,%3}, [%4];"
                 : "=r"(r0), "=r"(r1), "=r"(r2), "=r"(r3) : "r"(addr));
}
__device__ __forceinline__ void ldsm4t(unsigned int& r0, unsigned int& r1,
                                       unsigned int& r2, unsigned int& r3,
                                       unsigned int addr) {
    asm volatile("ldmatrix.sync.aligned.m8n8.x4.trans.shared.b16 {%0,%1,%2,%3}, [%4];"
                 : "=r"(r0), "=r"(r1), "=r"(r2), "=r"(r3) : "r"(addr));
}

// ---------------------------------------------------------------------------
// Merged fp32 -> bf16 hi/lo split kernel
// ---------------------------------------------------------------------------
#define XPAIRS (M_ * D_ / 2)
#define WPAIRS (D_ * D_ / 2)

__global__ void split_all_kernel(const float* __restrict__ x,
                                 const float* __restrict__ wq,
                                 const float* __restrict__ wk,
                                 const float* __restrict__ wv,
                                 const float* __restrict__ wo,
                                 __nv_bfloat16* __restrict__ xhi,
                                 __nv_bfloat16* __restrict__ xlo,
                                 __nv_bfloat16* __restrict__ whi,
                                 __nv_bfloat16* __restrict__ wlo) {
    long t = (long)blockIdx.x * blockDim.x + threadIdx.x;
    const long total = XPAIRS + 4L * WPAIRS;
    if (t >= total) return;
    const float* src;
    __nv_bfloat16 *dhi, *dlo;
    long idx;
    if (t < XPAIRS) {
        src = x; dhi = xhi; dlo = xlo; idx = t;
    } else {
        long wt = t - XPAIRS;
        int sel = (int)(wt / WPAIRS);
        idx = wt - (long)sel * WPAIRS;
        src = (sel == 0) ? wq : (sel == 1) ? wk : (sel == 2) ? wv : wo;
        dhi = whi + (long)sel * D_ * D_;
        dlo = wlo + (long)sel * D_ * D_;
    }
    float2 u = *(const float2*)(src + idx * 2);
    unsigned int hi, lo;
    split2(u.x, u.y, hi, lo);
    *(unsigned int*)(dhi + idx * 2) = hi;
    *(unsigned int*)(dlo + idx * 2) = lo;
}

// ---------------------------------------------------------------------------
// bf16 pre-split 3-term GEMM, 256x128 block tile, 8 warps (4x2), 64x64 warp
// tile. Term-major MMA ordering (dependency distance 16).
// MODE 0: fp32 store. 1: rope+scale+split (Q). 2: rope+split (K). 3: split (V).
// ---------------------------------------------------------------------------
#define BM 256
#define BN 128
#define GK 32
#define ASTR 40
#define BSTR 136
#define A_ELE (BM * ASTR)
#define B_ELE (GK * BSTR)
#define STG_ELE (2 * A_ELE + 2 * B_ELE)
#define GEMM_SMEM (STG_ELE * 2 * 2)

template <int MODE>
__device__ __forceinline__ void gemm_core_bf16(
    const __nv_bfloat16* __restrict__ Ahi, const __nv_bfloat16* __restrict__ Alo,
    const __nv_bfloat16* __restrict__ Bhi, const __nv_bfloat16* __restrict__ Blo,
    float* __restrict__ C,
    __nv_bfloat16* __restrict__ Dhi, __nv_bfloat16* __restrict__ Dlo,
    const float* __restrict__ fc, const float* __restrict__ fs,
    int N, int K, int bm, int bn) {
    extern __shared__ __nv_bfloat16 smG[];

    const int tid = threadIdx.x;
    const int wid = tid >> 5;
    const int lane = tid & 31;
    const int wm = (wid >> 1) * 64;
    const int wn = (wid & 1) * 64;
    const int g = lane >> 2;
    const int t4 = lane & 3;
    const int grp = lane >> 3;
    const int rr = lane & 7;

    const unsigned int smbase = (unsigned int)__cvta_generic_to_shared(smG);
    const unsigned int offAhi = 0;
    const unsigned int offAlo = A_ELE;
    const unsigned int offBhi = 2 * A_ELE;
    const unsigned int offBlo = 2 * A_ELE + B_ELE;

    float cc[4][8][4];
#pragma unroll
    for (int i = 0; i < 4; i++)
#pragma unroll
        for (int j = 0; j < 8; j++)
#pragma unroll
            for (int r = 0; r < 4; r++) cc[i][j][r] = 0.f;

    const int Kt = K / GK;

    auto issue_stage = [&](int kt, int buf) {
        const unsigned int sb = smbase + (unsigned)buf * STG_ELE * 2;
#pragma unroll
        for (int i = 0; i < 4; i++) {
            const int ch = tid + i * 256;
            const int row = ch >> 2;
            const int c = ch & 3;
            const long goff = (long)(bm + row) * K + kt * GK + c * 8;
            cp_async16(sb + (offAhi + (unsigned)(row * ASTR + c * 8)) * 2, Ahi + goff);
            cp_async16(sb + (offAlo + (unsigned)(row * ASTR + c * 8)) * 2, Alo + goff);
        }
#pragma unroll
        for (int i = 0; i < 2; i++) {
            const int ch = tid + i * 256;
            const int row = ch >> 4;
            const int c = ch & 15;
            const long goff = (long)(kt * GK + row) * N + bn + c * 8;
            cp_async16(sb + (offBhi + (unsigned)(row * BSTR + c * 8)) * 2, Bhi + goff);
            cp_async16(sb + (offBlo + (unsigned)(row * BSTR + c * 8)) * 2, Blo + goff);
        }
        cp_commit();
    };

    issue_stage(0, 0);

    for (int kt = 0; kt < Kt; kt++) {
        const int buf = kt & 1;
        if (kt + 1 < Kt) {
            issue_stage(kt + 1, buf ^ 1);
            cp_wait<1>();
        } else {
            cp_wait<0>();
        }
        __syncthreads();

        const __nv_bfloat16* sAhi = smG + buf * STG_ELE + offAhi;
        const __nv_bfloat16* sAlo = smG + buf * STG_ELE + offAlo;
        const __nv_bfloat16* sBhi = smG + buf * STG_ELE + offBhi;
        const __nv_bfloat16* sBlo = smG + buf * STG_ELE + offBlo;

#pragma unroll
        for (int ks = 0; ks < 2; ks++) {
            const int arow_in = (grp & 1) * 8 + rr;
            const int acol = ks * 16 + (grp >> 1) * 8;
            unsigned int ah[4][4], al[4][4];
#pragma unroll
            for (int mt = 0; mt < 4; mt++) {
                const int r0 = wm + mt * 16 + arow_in;
                unsigned int addr_h = (unsigned int)__cvta_generic_to_shared(
                    sAhi + r0 * ASTR + acol);
                ldsm4(ah[mt][0], ah[mt][1], ah[mt][2], ah[mt][3], addr_h);
                unsigned int addr_l = (unsigned int)__cvta_generic_to_shared(
                    sAlo + r0 * ASTR + acol);
                ldsm4(al[mt][0], al[mt][1], al[mt][2], al[mt][3], addr_l);
            }
            const int brow = ks * 16 + (grp & 1) * 8 + rr;
#pragma unroll
            for (int half = 0; half < 2; half++) {
                // Load B frags for np = 2*half, 2*half+1
                unsigned int bh[2][2][2], bl[2][2][2];   // [npl][nt-of-pair][2]
#pragma unroll
                for (int npl = 0; npl < 2; npl++) {
                    const int np = half * 2 + npl;
                    const int colsel = wn + np * 16 + ((grp & 2) ? 8 : 0);
                    unsigned int addr_h = (unsigned int)__cvta_generic_to_shared(
                        sBhi + brow * BSTR + colsel);
                    ldsm4t(bh[npl][0][0], bh[npl][0][1], bh[npl][1][0], bh[npl][1][1], addr_h);
                    unsigned int addr_l = (unsigned int)__cvta_generic_to_shared(
                        sBlo + brow * BSTR + colsel);
                    ldsm4t(bl[npl][0][0], bl[npl][0][1], bl[npl][1][0], bl[npl][1][1], addr_l);
                }
                // Term pass 1: ah * bl  (16 independent MMAs)
#pragma unroll
                for (int npl = 0; npl < 2; npl++)
#pragma unroll
                    for (int mt = 0; mt < 4; mt++) {
                        const int np = half * 2 + npl;
                        mma_bf16(cc[mt][2 * np],     ah[mt], bl[npl][0]);
                        mma_bf16(cc[mt][2 * np + 1], ah[mt], bl[npl][1]);
                    }
                // Term pass 2: al * bh
#pragma unroll
                for (int npl = 0; npl < 2; npl++)
#pragma unroll
                    for (int mt = 0; mt < 4; mt++) {
                        const int np = half * 2 + npl;
                        mma_bf16(cc[mt][2 * np],     al[mt], bh[npl][0]);
                        mma_bf16(cc[mt][2 * np + 1], al[mt], bh[npl][1]);
                    }
                // Term pass 3: ah * bh
#pragma unroll
                for (int npl = 0; npl < 2; npl++)
#pragma unroll
                    for (int mt = 0; mt < 4; mt++) {
                        const int np = half * 2 + npl;
                        mma_bf16(cc[mt][2 * np],     ah[mt], bh[npl][0]);
                        mma_bf16(cc[mt][2 * np + 1], ah[mt], bh[npl][1]);
                    }
            }
        }
        __syncthreads();
    }

    // Epilogue
#pragma unroll
    for (int mt = 0; mt < 4; mt++) {
#pragma unroll
        for (int nt = 0; nt < 8; nt++) {
            const int row = bm + wm + mt * 16 + g;
            const int col = bn + wn + nt * 8 + 2 * t4;
            if (MODE == 0) {
                *(float2*)(C + (long)row * N + col) =
                    make_float2(cc[mt][nt][0], cc[mt][nt][1]);
                *(float2*)(C + (long)(row + 8) * N + col) =
                    make_float2(cc[mt][nt][2], cc[mt][nt][3]);
            } else {
                const int p = (col & 63) >> 1;
#pragma unroll
                for (int rp = 0; rp < 2; rp++) {
                    const int r = row + rp * 8;
                    float x = cc[mt][nt][rp * 2];
                    float y = cc[mt][nt][rp * 2 + 1];
                    if (MODE == 1 || MODE == 2) {
                        const int s = r & (S_ - 1);
                        float c = fc[s * 32 + p];
                        float sn = fs[s * 32 + p];
                        float xr = x * c - y * sn;
                        float yr = x * sn + y * c;
                        if (MODE == 1) { xr *= QSCALE; yr *= QSCALE; }
                        x = xr; y = yr;
                    }
                    unsigned int hi, lo;
                    split2(x, y, hi, lo);
                    *(unsigned int*)(Dhi + (long)r * N + col) = hi;
                    *(unsigned int*)(Dlo + (long)r * N + col) = lo;
                }
            }
        }
    }
}

// Merged QKV projection + RoPE + split: blockIdx.x in [0,24).
__global__ __launch_bounds__(256, 1) void qkv_gemm(
    const __nv_bfloat16* __restrict__ xhi, const __nv_bfloat16* __restrict__ xlo,
    const __nv_bfloat16* __restrict__ whi, const __nv_bfloat16* __restrict__ wlo,
    const float* __restrict__ fc, const float* __restrict__ fs,
    __nv_bfloat16* __restrict__ qhi, __nv_bfloat16* __restrict__ qlo,
    __nv_bfloat16* __restrict__ khi, __nv_bfloat16* __restrict__ klo,
    __nv_bfloat16* __restrict__ vhi, __nv_bfloat16* __restrict__ vlo) {
    const int sel = blockIdx.x >> 3;
    const int bn = (blockIdx.x & 7) * BN;
    const int bm = blockIdx.y * BM;
    const __nv_bfloat16* Whi = whi + (long)sel * D_ * D_;
    const __nv_bfloat16* Wlo = wlo + (long)sel * D_ * D_;
    if (sel == 0)
        gemm_core_bf16<1>(xhi, xlo, Whi, Wlo, nullptr, qhi, qlo, fc, fs,
                          D_, D_, bm, bn);
    else if (sel == 1)
        gemm_core_bf16<2>(xhi, xlo, Whi, Wlo, nullptr, khi, klo, fc, fs,
                          D_, D_, bm, bn);
    else
        gemm_core_bf16<3>(xhi, xlo, Whi, Wlo, nullptr, vhi, vlo, nullptr, nullptr,
                          D_, D_, bm, bn);
}

__global__ __launch_bounds__(256, 1) void out_gemm(
    const __nv_bfloat16* __restrict__ ahi, const __nv_bfloat16* __restrict__ alo,
    const __nv_bfloat16* __restrict__ whi, const __nv_bfloat16* __restrict__ wlo,
    float* __restrict__ C) {
    gemm_core_bf16<0>(ahi, alo, whi + 3L * D_ * D_, wlo + 3L * D_ * D_, C,
                      nullptr, nullptr, nullptr, nullptr,
                      D_, D_, blockIdx.y * BM, blockIdx.x * BN);
}

// ---------------------------------------------------------------------------
// Flash attention: 64-row Q tile, 128 threads. Term-major MMA ordering.
// Pre-split bf16 in AND out, cp.async double-buffered K/V.
// ---------------------------------------------------------------------------
#define KP 72
#define TILE_E (64 * KP)
#define FLASH_SMEM (8 * TILE_E * 2)

__global__ __launch_bounds__(128) void flash2(
    const __nv_bfloat16* __restrict__ qhi, const __nv_bfloat16* __restrict__ qlo,
    const __nv_bfloat16* __restrict__ khi, const __nv_bfloat16* __restrict__ klo,
    const __nv_bfloat16* __restrict__ vhi, const __nv_bfloat16* __restrict__ vlo,
    __nv_bfloat16* __restrict__ ohi, __nv_bfloat16* __restrict__ olo) {
    extern __shared__ __nv_bfloat16 smB[];

    const int tid = threadIdx.x;
    const int lane = tid & 31;
    const int wid = tid >> 5;
    const int g = lane >> 2;
    const int t4 = lane & 3;
    const int wrow = wid * 16;
    const int grp = lane >> 3;
    const int rr  = lane & 7;

    const int qt = blockIdx.x;
    const int bh = blockIdx.y;
    const int q0 = qt * 64;

    const long headoff = (long)(bh >> 4) * S_ * D_ + (bh & 15) * HD_;
    const __nv_bfloat16* srcp[4] = {khi + headoff, klo + headoff,
                                    vhi + headoff, vlo + headoff};

    const unsigned int smbase = (unsigned int)__cvta_generic_to_shared(smB);

    unsigned int qh[4][4], ql[4][4];
    {
        const __nv_bfloat16* qhb = qhi + headoff;
        const __nv_bfloat16* qlb = qlo + headoff;
        const long r0 = (long)(q0 + wrow + g) * D_;
        const long r1 = (long)(q0 + wrow + g + 8) * D_;
#pragma unroll
        for (int kc = 0; kc < 4; kc++) {
            const int cb = kc * 16 + 2 * t4;
            qh[kc][0] = *(const unsigned int*)(qhb + r0 + cb);
            qh[kc][1] = *(const unsigned int*)(qhb + r1 + cb);
            qh[kc][2] = *(const unsigned int*)(qhb + r0 + cb + 8);
            qh[kc][3] = *(const unsigned int*)(qhb + r1 + cb + 8);
            ql[kc][0] = *(const unsigned int*)(qlb + r0 + cb);
            ql[kc][1] = *(const unsigned int*)(qlb + r1 + cb);
            ql[kc][2] = *(const unsigned int*)(qlb + r0 + cb + 8);
            ql[kc][3] = *(const unsigned int*)(qlb + r1 + cb + 8);
        }
    }

    auto issue = [&](int jt, int buf) {
        const int k0 = jt * 64;
#pragma unroll
        for (int i = 0; i < 16; i++) {
            const int G = tid + i * 128;
            const int arr = G >> 9;
            const int rem = G & 511;
            const int row = rem >> 3;
            const int ch = rem & 7;
            unsigned int dst = smbase +
                ((unsigned)((buf * 4 + arr) * TILE_E + row * KP + ch * 8)) * 2;
            cp_async16(dst, srcp[arr] + ((long)(k0 + row) * D_ + ch * 8));
        }
        cp_commit();
    };

    float oacc[8][4];
#pragma unroll
    for (int nt = 0; nt < 8; nt++)
#pragma unroll
        for (int r = 0; r < 4; r++) oacc[nt][r] = 0.f;
    float m0 = -1e30f, m1 = -1e30f, l0 = 0.f, l1 = 0.f;

    const int ntiles = qt + 1;
    issue(0, 0);

    for (int jt = 0; jt < ntiles; jt++) {
        const int buf = jt & 1;
        if (jt + 1 < ntiles) {
            issue(jt + 1, buf ^ 1);
            cp_wait<1>();
        } else {
            cp_wait<0>();
        }
        __syncthreads();

        const __nv_bfloat16* kh_s = smB + (buf * 4 + 0) * TILE_E;
        const __nv_bfloat16* kl_s = smB + (buf * 4 + 1) * TILE_E;
        const __nv_bfloat16* vh_s = smB + (buf * 4 + 2) * TILE_E;
        const __nv_bfloat16* vl_s = smB + (buf * 4 + 3) * TILE_E;

        float sc[8][4];
#pragma unroll
        for (int nt = 0; nt < 8; nt++)
#pragma unroll
            for (int r = 0; r < 4; r++) sc[nt][r] = 0.f;

        // ---- QK: per dc, load all 4 np K-frags, then 3 term passes of 8 ----
#pragma unroll
        for (int dc = 0; dc < 4; dc++) {
            unsigned int kbh[4][2][2], kbl[4][2][2];
#pragma unroll
            for (int np = 0; np < 4; np++) {
                const int ntA = 2 * np, ntB = 2 * np + 1;
                const int keysel = (grp & 2) ? ntB : ntA;
                const int colsel = dc * 16 + ((grp & 1) ? 8 : 0);
                unsigned int ahh = (unsigned int)__cvta_generic_to_shared(
                    kh_s + (keysel * 8 + rr) * KP + colsel);
                ldsm4(kbh[np][0][0], kbh[np][0][1], kbh[np][1][0], kbh[np][1][1], ahh);
                unsigned int ahl = (unsigned int)__cvta_generic_to_shared(
                    kl_s + (keysel * 8 + rr) * KP + colsel);
                ldsm4(kbl[np][0][0], kbl[np][0][1], kbl[np][1][0], kbl[np][1][1], ahl);
            }
#pragma unroll
            for (int np = 0; np < 4; np++) {
                mma_bf16(sc[2 * np],     qh[dc], kbl[np][0]);
                mma_bf16(sc[2 * np + 1], qh[dc], kbl[np][1]);
            }
#pragma unroll
            for (int np = 0; np < 4; np++) {
                mma_bf16(sc[2 * np],     ql[dc], kbh[np][0]);
                mma_bf16(sc[2 * np + 1], ql[dc], kbh[np][1]);
            }
#pragma unroll
            for (int np = 0; np < 4; np++) {
                mma_bf16(sc[2 * np],     qh[dc], kbh[np][0]);
                mma_bf16(sc[2 * np + 1], qh[dc], kbh[np][1]);
            }
        }

        if (jt == qt) {
            const int r0l = wrow + g;
#pragma unroll
            for (int nt = 0; nt < 8; nt++) {
                const int c = nt * 8 + 2 * t4;
                if (c > r0l)          sc[nt][0] = -1e30f;
                if (c + 1 > r0l)      sc[nt][1] = -1e30f;
                if (c > r0l + 8)      sc[nt][2] = -1e30f;
                if (c + 1 > r0l + 8)  sc[nt][3] = -1e30f;
            }
        }

        float tm0 = -1e30f, tm1 = -1e30f;
#pragma unroll
        for (int nt = 0; nt < 8; nt++) {
            tm0 = fmaxf(tm0, fmaxf(sc[nt][0], sc[nt][1]));
            tm1 = fmaxf(tm1, fmaxf(sc[nt][2], sc[nt][3]));
        }
        tm0 = fmaxf(tm0, __shfl_xor_sync(0xffffffffu, tm0, 1));
        tm0 = fmaxf(tm0, __shfl_xor_sync(0xffffffffu, tm0, 2));
        tm1 = fmaxf(tm1, __shfl_xor_sync(0xffffffffu, tm1, 1));
        tm1 = fmaxf(tm1, __shfl_xor_sync(0xffffffffu, tm1, 2));

        float mn0 = fmaxf(m0, tm0);
        float mn1 = fmaxf(m1, tm1);
        float al0 = ex2f(m0 - mn0);
        float al1 = ex2f(m1 - mn1);
        m0 = mn0; m1 = mn1;

        float ps0 = 0.f, ps1 = 0.f;
#pragma unroll
        for (int nt = 0; nt < 8; nt++) {
            sc[nt][0] = ex2f(sc[nt][0] - m0);
            sc[nt][1] = ex2f(sc[nt][1] - m0);
            sc[nt][2] = ex2f(sc[nt][2] - m1);
            sc[nt][3] = ex2f(sc[nt][3] - m1);
            ps0 += sc[nt][0] + sc[nt][1];
            ps1 += sc[nt][2] + sc[nt][3];
        }
        ps0 += __shfl_xor_sync(0xffffffffu, ps0, 1);
        ps0 += __shfl_xor_sync(0xffffffffu, ps0, 2);
        ps1 += __shfl_xor_sync(0xffffffffu, ps1, 1);
        ps1 += __shfl_xor_sync(0xffffffffu, ps1, 2);
        l0 = l0 * al0 + ps0;
        l1 = l1 * al1 + ps1;

#pragma unroll
        for (int nt = 0; nt < 8; nt++) {
            oacc[nt][0] *= al0; oacc[nt][1] *= al0;
            oacc[nt][2] *= al1; oacc[nt][3] *= al1;
        }

        // ---- PV: per kc, load all 4 np V-frags, then 3 term passes of 8 ----
#pragma unroll
        for (int kc = 0; kc < 4; kc++) {
            unsigned int ph[4], pl[4];
            split2(sc[2 * kc][0], sc[2 * kc][1], ph[0], pl[0]);
            split2(sc[2 * kc][2], sc[2 * kc][3], ph[1], pl[1]);
            split2(sc[2 * kc + 1][0], sc[2 * kc + 1][1], ph[2], pl[2]);
            split2(sc[2 * kc + 1][2], sc[2 * kc + 1][3], ph[3], pl[3]);

            unsigned int vbh[4][2][2], vbl[4][2][2];
#pragma unroll
            for (int np = 0; np < 4; np++) {
                const int ntA = 2 * np, ntB = 2 * np + 1;
                const int rowsel = kc * 16 + ((grp & 1) ? 8 : 0) + rr;
                const int colsel = ((grp & 2) ? ntB : ntA) * 8;
                unsigned int avh = (unsigned int)__cvta_generic_to_shared(
                    vh_s + rowsel * KP + colsel);
                ldsm4t(vbh[np][0][0], vbh[np][0][1], vbh[np][1][0], vbh[np][1][1], avh);
                unsigned int avl = (unsigned int)__cvta_generic_to_shared(
                    vl_s + rowsel * KP + colsel);
                ldsm4t(vbl[np][0][0], vbl[np][0][1], vbl[np][1][0], vbl[np][1][1], avl);
            }
#pragma unroll
            for (int np = 0; np < 4; np++) {
                mma_bf16(oacc[2 * np],     ph, vbl[np][0]);
                mma_bf16(oacc[2 * np + 1], ph, vbl[np][1]);
            }
#pragma unroll
            for (int np = 0; np < 4; np++) {
                mma_bf16(oacc[2 * np],     pl, vbh[np][0]);
                mma_bf16(oacc[2 * np + 1], pl, vbh[np][1]);
            }
#pragma unroll
            for (int np = 0; np < 4; np++) {
                mma_bf16(oacc[2 * np],     ph, vbh[np][0]);
                mma_bf16(oacc[2 * np + 1], ph, vbh[np][1]);
            }
        }
        __syncthreads();
    }

    const float inv0 = 1.f / l0;
    const float inv1 = 1.f / l1;
    const int row0 = q0 + wrow + g;
    __nv_bfloat16* ohb = ohi + headoff;
    __nv_bfloat16* olb = olo + headoff;
#pragma unroll
    for (int nt = 0; nt < 8; nt++) {
        const int col = nt * 8 + 2 * t4;
        unsigned int hi, lo;
        split2(oacc[nt][0] * inv0, oacc[nt][1] * inv0, hi, lo);
        *(unsigned int*)(ohb + (long)row0 * D_ + col) = hi;
        *(unsigned int*)(olb + (long)row0 * D_ + col) = lo;
        split2(oacc[nt][2] * inv1, oacc[nt][3] * inv1, hi, lo);
        *(unsigned int*)(ohb + (long)(row0 + 8) * D_ + col) = hi;
        *(unsigned int*)(olb + (long)(row0 + 8) * D_ + col) = lo;
    }
}

// ---------------------------------------------------------------------------
// Launch
// ---------------------------------------------------------------------------
extern "C" void kernel_launch(void* const* d_in, const int* in_sizes, int n_in,
                              void* d_out, int out_size) {
    const float* x  = (const float*)d_in[0];
    const float* wq = (const float*)d_in[1];
    const float* wk = (const float*)d_in[2];
    const float* wv = (const float*)d_in[3];
    const float* wo = (const float*)d_in[4];
    const float* fc = (const float*)d_in[5];
    const float* fs = (const float*)d_in[6];
    float* out = (float*)d_out;

    __nv_bfloat16 *xhi, *xlo, *whi, *wlo;
    __nv_bfloat16 *qhi, *qlo, *khi, *klo, *vhi, *vlo, *ahi, *alo;
    cudaGetSymbolAddress((void**)&xhi, g_xhi);
    cudaGetSymbolAddress((void**)&xlo, g_xlo);
    cudaGetSymbolAddress((void**)&whi, g_whi);
    cudaGetSymbolAddress((void**)&wlo, g_wlo);
    cudaGetSymbolAddress((void**)&qhi, g_qhi);
    cudaGetSymbolAddress((void**)&qlo, g_qlo);
    cudaGetSymbolAddress((void**)&khi, g_khi);
    cudaGetSymbolAddress((void**)&klo, g_klo);
    cudaGetSymbolAddress((void**)&vhi, g_vhi);
    cudaGetSymbolAddress((void**)&vlo, g_vlo);
    cudaGetSymbolAddress((void**)&ahi, g_ahi);
    cudaGetSymbolAddress((void**)&alo, g_alo);

    const long split_total = XPAIRS + 4L * WPAIRS;
    split_all_kernel<<<(int)((split_total + 255) / 256), 256>>>(
        x, wq, wk, wv, wo, xhi, xlo, whi, wlo);

    cudaFuncSetAttribute(qkv_gemm, cudaFuncAttributeMaxDynamicSharedMemorySize,
                         GEMM_SMEM);
    cudaFuncSetAttribute(out_gemm, cudaFuncAttributeMaxDynamicSharedMemorySize,
                         GEMM_SMEM);

    qkv_gemm<<<dim3(24, M_ / BM), 256, GEMM_SMEM>>>(xhi, xlo, whi, wlo, fc, fs,
                                                    qhi, qlo, khi, klo, vhi, vlo);

    cudaFuncSetAttribute(flash2, cudaFuncAttributeMaxDynamicSharedMemorySize,
                         FLASH_SMEM);
    flash2<<<dim3(S_ / 64, B_ * H_), 128, FLASH_SMEM>>>(qhi, qlo, khi, klo,
                                                        vhi, vlo, ahi, alo);

    out_gemm<<<dim3(D_ / BN, M_ / BM), 256, GEMM_SMEM>>>(ahi, alo, whi, wlo, out);
}